// round 2
// baseline (speedup 1.0000x reference)
#include <cuda_runtime.h>
#include <math.h>

#define BB 4
#define NN 8192
#define FF 64
#define IN_DIM 67
#define IN_PAD 68
#define H1 64
#define H2 32

// ---- scratch (no allocation allowed) ----
__device__ int g_nleaf[BB];

// ============================================================
// Kernel 0: count leaf mask per batch (mask is int32: 0/1)
// ============================================================
__global__ void count_mask_kernel(const int* __restrict__ mask) {
    int b = blockIdx.x;
    int tid = threadIdx.x;
    const int* m = mask + b * NN;
    int c = 0;
    for (int i = tid; i < NN; i += blockDim.x) c += (m[i] != 0);
    for (int o = 16; o; o >>= 1) c += __shfl_down_sync(0xFFFFFFFFu, c, o);
    __shared__ int ws[8];
    if ((tid & 31) == 0) ws[tid >> 5] = c;
    __syncthreads();
    if (tid == 0) {
        int t = 0;
        for (int w = 0; w < (int)(blockDim.x >> 5); w++) t += ws[w];
        g_nleaf[b] = t;
    }
}

// ============================================================
// Kernel 1: per-point MLP 67 -> 64 -> 32 -> 1 (+mask, +n_leaf gate)
// Weights in smem, broadcast LDS.128, 8 parallel accumulator chains.
// Also writes the features passthrough (data already in registers).
// ============================================================
__global__ __launch_bounds__(256) void mlp_kernel(
    const float* __restrict__ points, const float* __restrict__ features,
    const int* __restrict__ mask,
    const float* __restrict__ W1, const float* __restrict__ b1,
    const float* __restrict__ W2, const float* __restrict__ b2,
    const float* __restrict__ W3, const float* __restrict__ b3,
    float* __restrict__ scores, float* __restrict__ out_feats)
{
    __shared__ float sW1[H1][IN_PAD];
    __shared__ float sb1[H1];
    __shared__ float sW2[H2][H1];
    __shared__ float sb2[H2];
    __shared__ float sW3[H2];
    __shared__ float sb3;

    int tid = threadIdx.x;
    for (int i = tid; i < H1 * IN_PAD; i += 256) {
        int j = i / IN_PAD, k = i % IN_PAD;
        sW1[j][k] = (k < IN_DIM) ? W1[j * IN_DIM + k] : 0.0f;
    }
    for (int i = tid; i < H2 * H1; i += 256) sW2[i / H1][i % H1] = W2[i];
    if (tid < H1) sb1[tid] = b1[tid];
    if (tid < H2) { sb2[tid] = b2[tid]; sW3[tid] = W3[tid]; }
    if (tid == 0) sb3 = b3[0];
    __syncthreads();

    int p = blockIdx.x * 256 + tid;   // global point id over B*N (grid exact)
    int b = p >> 13;                  // p / 8192

    // load input vector [feat(64), xyz(3), 0] + stream features to output
    float x[IN_PAD];
    const float4* f4 = (const float4*)(features + (size_t)p * FF);
    float4* o4 = (float4*)(out_feats + (size_t)p * FF);
#pragma unroll
    for (int i = 0; i < FF / 4; i++) {
        float4 v = f4[i];
        o4[i] = v;
        x[4 * i + 0] = v.x; x[4 * i + 1] = v.y;
        x[4 * i + 2] = v.z; x[4 * i + 3] = v.w;
    }
    const float* pp = points + (size_t)p * 3;
    x[64] = pp[0]; x[65] = pp[1]; x[66] = pp[2]; x[67] = 0.0f;

    // layer 1: 64 outputs, groups of 8 independent chains
    float h1v[H1];
#pragma unroll
    for (int jg = 0; jg < H1; jg += 8) {
        float acc[8];
#pragma unroll
        for (int jj = 0; jj < 8; jj++) acc[jj] = sb1[jg + jj];
#pragma unroll
        for (int k = 0; k < IN_PAD; k += 4) {
#pragma unroll
            for (int jj = 0; jj < 8; jj++) {
                float4 w = *(const float4*)&sW1[jg + jj][k];
                acc[jj] += w.x * x[k] + w.y * x[k + 1] + w.z * x[k + 2] + w.w * x[k + 3];
            }
        }
#pragma unroll
        for (int jj = 0; jj < 8; jj++) h1v[jg + jj] = fmaxf(acc[jj], 0.0f);
    }

    // layer 2: 32 outputs
    float h2v[H2];
#pragma unroll
    for (int jg = 0; jg < H2; jg += 8) {
        float acc[8];
#pragma unroll
        for (int jj = 0; jj < 8; jj++) acc[jj] = sb2[jg + jj];
#pragma unroll
        for (int k = 0; k < H1; k += 4) {
#pragma unroll
            for (int jj = 0; jj < 8; jj++) {
                float4 w = *(const float4*)&sW2[jg + jj][k];
                acc[jj] += w.x * h1v[k] + w.y * h1v[k + 1] + w.z * h1v[k + 2] + w.w * h1v[k + 3];
            }
        }
#pragma unroll
        for (int jj = 0; jj < 8; jj++) h2v[jg + jj] = fmaxf(acc[jj], 0.0f);
    }

    // layer 3: 1 output, 4 chains
    float a0 = 0.f, a1 = 0.f, a2 = 0.f, a3 = 0.f;
#pragma unroll
    for (int k = 0; k < H2; k += 4) {
        a0 += sW3[k + 0] * h2v[k + 0];
        a1 += sW3[k + 1] * h2v[k + 1];
        a2 += sW3[k + 2] * h2v[k + 2];
        a3 += sW3[k + 3] * h2v[k + 3];
    }
    float z = sb3 + (a0 + a1) + (a2 + a3);
    float s = 1.0f / (1.0f + expf(-z));

    float score = (mask[p] != 0) ? s : 0.0f;
    if (g_nleaf[b] < 10) score = 0.0f;
    scores[p] = score;
}

// ============================================================
// Kernel 2: per-batch confidence.
// clarity = unbiased masked var of scores (masked-out scores are exactly 0,
//   so sum/sumsq over all N equal the masked sums).
// sel compaction in ascending index order == argsort(where(sel,idx,N+idx))
//   prefix: distances between consecutive selected points, unbiased var.
// ============================================================
__global__ __launch_bounds__(256) void conf_kernel(
    const float* __restrict__ scores, const float* __restrict__ points,
    float* __restrict__ conf_out)
{
    __shared__ int sel[NN];           // 32 KB
    __shared__ int wtot[8], woff[8];
    __shared__ float wsum[8], wsq[8], wsd[8], wsd2[8];
    __shared__ int s_cnt;

    int b = blockIdx.x;
    int tid = threadIdx.x;
    int lane = tid & 31, warp = tid >> 5;
    const float* s = scores + b * NN;
    const float* P = points + (size_t)b * NN * 3;

    // pass 1: sums + per-thread selected count (each thread owns 32 contiguous idx)
    int base = tid * 32;
    float sum = 0.0f, sumsq = 0.0f;
    int c = 0;
    for (int i = 0; i < 32; i++) {
        float v = s[base + i];
        sum += v; sumsq += v * v;
        c += (v > 0.7f);
    }
    // warp inclusive scan of counts
    int incl = c;
    for (int o = 1; o < 32; o <<= 1) {
        int t = __shfl_up_sync(0xFFFFFFFFu, incl, o);
        if (lane >= o) incl += t;
    }
    if (lane == 31) wtot[warp] = incl;
    // warp reduce sums
    float rs = sum, rq = sumsq;
    for (int o = 16; o; o >>= 1) {
        rs += __shfl_down_sync(0xFFFFFFFFu, rs, o);
        rq += __shfl_down_sync(0xFFFFFFFFu, rq, o);
    }
    if (lane == 0) { wsum[warp] = rs; wsq[warp] = rq; }
    __syncthreads();
    if (tid == 0) {
        int r = 0;
        for (int w = 0; w < 8; w++) { woff[w] = r; r += wtot[w]; }
        s_cnt = r;
    }
    __syncthreads();

    // pass 2: write selected indices in ascending order
    int off = woff[warp] + incl - c;
    for (int i = 0; i < 32; i++) {
        float v = s[base + i];
        if (v > 0.7f) sel[off++] = base + i;
    }
    __syncthreads();

    int cnt = s_cnt;
    int pc = cnt - 1;             // number of valid consecutive pairs
    float sd = 0.0f, sd2 = 0.0f;
    for (int q = tid; q < pc; q += 256) {
        int i1 = sel[q], i2 = sel[q + 1];
        float dx = P[i2 * 3 + 0] - P[i1 * 3 + 0];
        float dy = P[i2 * 3 + 1] - P[i1 * 3 + 1];
        float dz = P[i2 * 3 + 2] - P[i1 * 3 + 2];
        float d = sqrtf(dx * dx + dy * dy + dz * dz);
        sd += d; sd2 += d * d;
    }
    for (int o = 16; o; o >>= 1) {
        sd  += __shfl_down_sync(0xFFFFFFFFu, sd, o);
        sd2 += __shfl_down_sync(0xFFFFFFFFu, sd2, o);
    }
    if (lane == 0) { wsd[warp] = sd; wsd2[warp] = sd2; }
    __syncthreads();

    if (tid == 0) {
        float tsum = 0.f, tsq = 0.f, tsd = 0.f, tsd2 = 0.f;
        for (int w = 0; w < 8; w++) {
            tsum += wsum[w]; tsq += wsq[w]; tsd += wsd[w]; tsd2 += wsd2[w];
        }
        int nleaf = g_nleaf[b];
        float nl = (float)nleaf;
        float mean = tsum / fmaxf(nl, 1.0f);
        float clarity = (tsq - 2.0f * mean * tsum + mean * mean * nl)
                        / fmaxf(nl - 1.0f, 1.0f);
        float pcf = (float)(pc > 0 ? pc : 0);
        float meand = tsd / fmaxf(pcf, 1.0f);
        float dvar = (tsd2 - 2.0f * meand * tsd + meand * meand * pcf)
                     / fmaxf(pcf - 1.0f, 1.0f);
        float cont = fminf(fmaxf(1.0f / (dvar + 1e-8f), 0.0f), 1.0f);
        cont = (cnt > 5) ? cont : 0.0f;
        float conf = fminf(fmaxf(clarity * cont, 0.0f), 1.0f);
        conf = (nleaf == 0) ? 0.0f : conf;
        conf_out[b] = conf;
    }
}

// ============================================================
// launch
// ============================================================
extern "C" void kernel_launch(void* const* d_in, const int* in_sizes, int n_in,
                              void* d_out, int out_size) {
    const float* points   = (const float*)d_in[0];
    const float* features = (const float*)d_in[1];
    const int*   mask     = (const int*)d_in[2];
    const float* W1 = (const float*)d_in[3];
    const float* b1 = (const float*)d_in[4];
    const float* W2 = (const float*)d_in[5];
    const float* b2 = (const float*)d_in[6];
    const float* W3 = (const float*)d_in[7];
    const float* b3 = (const float*)d_in[8];

    float* out_scores = (float*)d_out;                       // [B*N]
    float* out_feats  = out_scores + BB * NN;                // [B*N*F]
    float* out_conf   = out_feats + (size_t)BB * NN * FF;    // [B]

    count_mask_kernel<<<BB, 256>>>(mask);

    mlp_kernel<<<(BB * NN) / 256, 256>>>(points, features, mask,
                                         W1, b1, W2, b2, W3, b3,
                                         out_scores, out_feats);

    conf_kernel<<<BB, 256>>>(out_scores, points, out_conf);
}

// round 3
// speedup vs baseline: 1.1099x; 1.1099x over previous
#include <cuda_runtime.h>
#include <math.h>

#define BB 4
#define NN 8192
#define FF 64
#define IN_DIM 67
#define IN_PAD 68
#define H1 64
#define H2 32

// ============================================================
// Kernel 1: per-point MLP 67 -> 64 -> 32 -> 1 (+mask)
// Layer-2 streaming: h1 produced in groups of 8, immediately folded
// into all 32 h2 accumulators -> no h1v[64] array -> no spills.
// Also writes the features passthrough (data already in registers).
// No n_leaf gate here (applied later in conf_kernel).
// ============================================================
__global__ __launch_bounds__(256) void mlp_kernel(
    const float* __restrict__ points, const float* __restrict__ features,
    const int* __restrict__ mask,
    const float* __restrict__ W1, const float* __restrict__ b1,
    const float* __restrict__ W2, const float* __restrict__ b2,
    const float* __restrict__ W3, const float* __restrict__ b3,
    float* __restrict__ scores, float* __restrict__ out_feats)
{
    __shared__ float sW1[H1][IN_PAD];
    __shared__ float sb1[H1];
    __shared__ float sW2[H2][H1];
    __shared__ float sW3[H2];
    __shared__ float sb2s[H2];
    __shared__ float sb3;

    int tid = threadIdx.x;
    for (int i = tid; i < H1 * IN_PAD; i += 256) {
        int j = i / IN_PAD, k = i % IN_PAD;
        sW1[j][k] = (k < IN_DIM) ? W1[j * IN_DIM + k] : 0.0f;
    }
    for (int i = tid; i < H2 * H1; i += 256) sW2[i / H1][i % H1] = W2[i];
    if (tid < H1) sb1[tid] = b1[tid];
    if (tid < H2) { sb2s[tid] = b2[tid]; sW3[tid] = W3[tid]; }
    if (tid == 0) sb3 = b3[0];
    __syncthreads();

    int p = blockIdx.x * 256 + tid;   // global point id over B*N (grid exact)

    // load input vector [feat(64), xyz(3), 0] + stream features to output
    float x[IN_PAD];
    const float4* f4 = (const float4*)(features + (size_t)p * FF);
    float4* o4 = (float4*)(out_feats + (size_t)p * FF);
#pragma unroll
    for (int i = 0; i < FF / 4; i++) {
        float4 v = f4[i];
        o4[i] = v;
        x[4 * i + 0] = v.x; x[4 * i + 1] = v.y;
        x[4 * i + 2] = v.z; x[4 * i + 3] = v.w;
    }
    const float* pp = points + (size_t)p * 3;
    x[64] = pp[0]; x[65] = pp[1]; x[66] = pp[2]; x[67] = 0.0f;

    // h2 accumulators initialized with bias
    float h2acc[H2];
#pragma unroll
    for (int j = 0; j < H2; j++) h2acc[j] = sb2s[j];

    // layer 1 in groups of 8 outputs, streamed straight into layer 2
#pragma unroll
    for (int jg = 0; jg < H1 / 8; jg++) {
        float acc[8];
#pragma unroll
        for (int jj = 0; jj < 8; jj++) acc[jj] = sb1[jg * 8 + jj];
#pragma unroll
        for (int k = 0; k < IN_PAD; k += 4) {
#pragma unroll
            for (int jj = 0; jj < 8; jj++) {
                float4 w = *(const float4*)&sW1[jg * 8 + jj][k];
                acc[jj] += w.x * x[k] + w.y * x[k + 1] + w.z * x[k + 2] + w.w * x[k + 3];
            }
        }
#pragma unroll
        for (int jj = 0; jj < 8; jj++) acc[jj] = fmaxf(acc[jj], 0.0f);

        // fold the 8 fresh h1 values into all 32 h2 accumulators
#pragma unroll
        for (int j2 = 0; j2 < H2; j2++) {
            float4 wa = *(const float4*)&sW2[j2][jg * 8];
            float4 wb = *(const float4*)&sW2[j2][jg * 8 + 4];
            h2acc[j2] += wa.x * acc[0] + wa.y * acc[1] + wa.z * acc[2] + wa.w * acc[3]
                       + wb.x * acc[4] + wb.y * acc[5] + wb.z * acc[6] + wb.w * acc[7];
        }
    }

    // layer 3: relu + dot, 4 chains
    float a0 = 0.f, a1 = 0.f, a2 = 0.f, a3 = 0.f;
#pragma unroll
    for (int k = 0; k < H2; k += 4) {
        a0 += sW3[k + 0] * fmaxf(h2acc[k + 0], 0.0f);
        a1 += sW3[k + 1] * fmaxf(h2acc[k + 1], 0.0f);
        a2 += sW3[k + 2] * fmaxf(h2acc[k + 2], 0.0f);
        a3 += sW3[k + 3] * fmaxf(h2acc[k + 3], 0.0f);
    }
    float z = sb3 + (a0 + a1) + (a2 + a3);
    float s = 1.0f / (1.0f + expf(-z));

    scores[p] = (mask[p] != 0) ? s : 0.0f;
}

// ============================================================
// Kernel 2: per-batch confidence + n_leaf gate. 1024 threads.
// Counts mask, gates scores (zeroing them in-place if n_leaf<10),
// clarity = unbiased masked var (masked-out scores are exactly 0),
// sel compaction ascending == the reference argsort order,
// distances of consecutive selected points, unbiased var, conf.
// ============================================================
__global__ __launch_bounds__(1024) void conf_kernel(
    const float* __restrict__ scores_in, const int* __restrict__ mask,
    const float* __restrict__ points,
    float* __restrict__ scores_out,   // same buffer, for gating writes
    float* __restrict__ conf_out)
{
    __shared__ int sel[NN];           // 32 KB
    __shared__ int wtot[32], woff[32];
    __shared__ float wsum[32], wsq[32], wsd[32], wsd2[32];
    __shared__ int s_cnt, s_nleaf;

    int b = blockIdx.x;
    int tid = threadIdx.x;
    int lane = tid & 31, warp = tid >> 5;
    const float* s = scores_in + b * NN;
    float* so = scores_out + b * NN;
    const float* P = points + (size_t)b * NN * 3;

    // phase 0: count mask (int4 loads: 2 per thread)
    {
        const int4* m4 = (const int4*)(mask + b * NN);
        int c = 0;
#pragma unroll
        for (int i = 0; i < 2; i++) {
            int4 v = m4[tid * 2 + i];
            c += (v.x != 0) + (v.y != 0) + (v.z != 0) + (v.w != 0);
        }
        for (int o = 16; o; o >>= 1) c += __shfl_down_sync(0xFFFFFFFFu, c, o);
        if (lane == 0) wtot[warp] = c;
        __syncthreads();
        if (tid == 0) {
            int t = 0;
            for (int w = 0; w < 32; w++) t += wtot[w];
            s_nleaf = t;
        }
        __syncthreads();
    }
    int nleaf = s_nleaf;
    bool gate_fail = (nleaf < 10);

    // phase 1: sums + per-thread selected count (thread owns 8 contiguous idx)
    int base = tid * 8;
    float sum = 0.0f, sumsq = 0.0f;
    int c = 0;
    float v8[8];
    {
        const float4* s4 = (const float4*)(s + base);
        float4 va = s4[0], vb = s4[1];
        v8[0] = va.x; v8[1] = va.y; v8[2] = va.z; v8[3] = va.w;
        v8[4] = vb.x; v8[5] = vb.y; v8[6] = vb.z; v8[7] = vb.w;
    }
    if (gate_fail) {
        // reference zeroes all scores for this batch
        float4 zz = make_float4(0.f, 0.f, 0.f, 0.f);
        ((float4*)(so + base))[0] = zz;
        ((float4*)(so + base))[1] = zz;
#pragma unroll
        for (int i = 0; i < 8; i++) v8[i] = 0.0f;
    }
#pragma unroll
    for (int i = 0; i < 8; i++) {
        float v = v8[i];
        sum += v; sumsq += v * v;
        c += (v > 0.7f);
    }
    // warp inclusive scan of counts
    int incl = c;
    for (int o = 1; o < 32; o <<= 1) {
        int t = __shfl_up_sync(0xFFFFFFFFu, incl, o);
        if (lane >= o) incl += t;
    }
    if (lane == 31) wtot[warp] = incl;
    // warp reduce sums
    float rs = sum, rq = sumsq;
    for (int o = 16; o; o >>= 1) {
        rs += __shfl_down_sync(0xFFFFFFFFu, rs, o);
        rq += __shfl_down_sync(0xFFFFFFFFu, rq, o);
    }
    if (lane == 0) { wsum[warp] = rs; wsq[warp] = rq; }
    __syncthreads();
    // warp 0 scans the 32 warp totals
    if (warp == 0) {
        int t = wtot[lane];
        int sc = t;
        for (int o = 1; o < 32; o <<= 1) {
            int u = __shfl_up_sync(0xFFFFFFFFu, sc, o);
            if (lane >= o) sc += u;
        }
        woff[lane] = sc - t;           // exclusive
        if (lane == 31) s_cnt = sc;
    }
    __syncthreads();

    // phase 2: write selected indices in ascending order
    int off = woff[warp] + incl - c;
#pragma unroll
    for (int i = 0; i < 8; i++) {
        if (v8[i] > 0.7f) sel[off++] = base + i;
    }
    __syncthreads();

    int cnt = s_cnt;
    int pc = cnt - 1;             // number of valid consecutive pairs
    float sd = 0.0f, sd2 = 0.0f;
    for (int q = tid; q < pc; q += 1024) {
        int i1 = sel[q], i2 = sel[q + 1];
        float dx = P[i2 * 3 + 0] - P[i1 * 3 + 0];
        float dy = P[i2 * 3 + 1] - P[i1 * 3 + 1];
        float dz = P[i2 * 3 + 2] - P[i1 * 3 + 2];
        float d = sqrtf(dx * dx + dy * dy + dz * dz);
        sd += d; sd2 += d * d;
    }
    for (int o = 16; o; o >>= 1) {
        sd  += __shfl_down_sync(0xFFFFFFFFu, sd, o);
        sd2 += __shfl_down_sync(0xFFFFFFFFu, sd2, o);
    }
    if (lane == 0) { wsd[warp] = sd; wsd2[warp] = sd2; }
    __syncthreads();

    if (tid == 0) {
        float tsum = 0.f, tsq = 0.f, tsd = 0.f, tsd2 = 0.f;
        for (int w = 0; w < 32; w++) {
            tsum += wsum[w]; tsq += wsq[w]; tsd += wsd[w]; tsd2 += wsd2[w];
        }
        float nl = (float)nleaf;
        float mean = tsum / fmaxf(nl, 1.0f);
        float clarity = (tsq - 2.0f * mean * tsum + mean * mean * nl)
                        / fmaxf(nl - 1.0f, 1.0f);
        float pcf = (float)(pc > 0 ? pc : 0);
        float meand = tsd / fmaxf(pcf, 1.0f);
        float dvar = (tsd2 - 2.0f * meand * tsd + meand * meand * pcf)
                     / fmaxf(pcf - 1.0f, 1.0f);
        float cont = fminf(fmaxf(1.0f / (dvar + 1e-8f), 0.0f), 1.0f);
        cont = (cnt > 5) ? cont : 0.0f;
        float conf = fminf(fmaxf(clarity * cont, 0.0f), 1.0f);
        conf = (nleaf == 0) ? 0.0f : conf;
        conf_out[b] = conf;
    }
}

// ============================================================
// launch
// ============================================================
extern "C" void kernel_launch(void* const* d_in, const int* in_sizes, int n_in,
                              void* d_out, int out_size) {
    const float* points   = (const float*)d_in[0];
    const float* features = (const float*)d_in[1];
    const int*   mask     = (const int*)d_in[2];
    const float* W1 = (const float*)d_in[3];
    const float* b1 = (const float*)d_in[4];
    const float* W2 = (const float*)d_in[5];
    const float* b2 = (const float*)d_in[6];
    const float* W3 = (const float*)d_in[7];
    const float* b3 = (const float*)d_in[8];

    float* out_scores = (float*)d_out;                       // [B*N]
    float* out_feats  = out_scores + BB * NN;                // [B*N*F]
    float* out_conf   = out_feats + (size_t)BB * NN * FF;    // [B]

    mlp_kernel<<<(BB * NN) / 256, 256>>>(points, features, mask,
                                         W1, b1, W2, b2, W3, b3,
                                         out_scores, out_feats);

    conf_kernel<<<BB, 1024>>>(out_scores, mask, points, out_scores, out_conf);
}

// round 4
// speedup vs baseline: 1.9001x; 1.7119x over previous
#include <cuda_runtime.h>
#include <cuda_fp16.h>
#include <math.h>

#define BB 4
#define NN 8192
#define FF 64
#define H1 64
#define H2 32
#define K2P 36            // padded half2 pairs per W1 row (67 inputs + bias + pad)

__device__ __forceinline__ __half2 u2h2(unsigned int u) {
    return *reinterpret_cast<__half2*>(&u);
}

// ============================================================
// Kernel 1: per-point MLP 67 -> 64 -> 32 -> 1 (+mask) in fp16x2.
// Weights packed to half2 in smem (done per-CTA), x packed to half2.
// Bias1 folded into K-slot 34 (x=1). Layer-1 output streamed in groups
// of 8 straight into 32 half2 layer-2 accumulators (no h1 array).
// fp32 horizontal combine + relu at layer boundaries; layer3+sigmoid fp32.
// Also writes the features passthrough (data already in registers).
// ============================================================
__global__ __launch_bounds__(256) void mlp_kernel(
    const float* __restrict__ points, const float* __restrict__ features,
    const int* __restrict__ mask,
    const float* __restrict__ W1, const float* __restrict__ b1,
    const float* __restrict__ W2, const float* __restrict__ b2,
    const float* __restrict__ W3, const float* __restrict__ b3,
    float* __restrict__ scores, float* __restrict__ out_feats)
{
    __shared__ __align__(16) __half2 sW1h[H1][K2P];   // 64*36*4B = 9216B
    __shared__ __align__(16) __half2 sW2h[H2][H1/2];  // 32*32*4B = 4096B
    __shared__ float sb2[H2];
    __shared__ float sW3[H2];
    __shared__ float sb3;

    int tid = threadIdx.x;

    // ---- pack W1 (+bias1) into half2 [64][36] ----
    for (int idx = tid; idx < H1 * K2P; idx += 256) {
        int j = idx / K2P, k2 = idx % K2P;
        float a = 0.f, bv = 0.f;
        if (k2 <= 33) {
            int k = 2 * k2;
            a  = (k     < 67) ? W1[j * 67 + k]     : 0.f;
            bv = (k + 1 < 67) ? W1[j * 67 + k + 1] : 0.f;
        } else if (k2 == 34) {
            a = b1[j];                 // bias slot, x2[34] = (1, 0)
        }
        sW1h[j][k2] = __floats2half2_rn(a, bv);
    }
    // ---- pack W2 into half2 [32][32] ----
    for (int idx = tid; idx < H2 * (H1 / 2); idx += 256) {
        int i = idx / (H1 / 2), j2 = idx % (H1 / 2);
        sW2h[i][j2] = __floats2half2_rn(W2[i * H1 + 2 * j2], W2[i * H1 + 2 * j2 + 1]);
    }
    if (tid < H2) { sb2[tid] = b2[tid]; sW3[tid] = W3[tid]; }
    if (tid == 0) sb3 = b3[0];
    __syncthreads();

    int p = blockIdx.x * 256 + tid;   // global point id over B*N (grid exact)

    // ---- load input, stream features passthrough, pack x to half2 ----
    __half2 x2[K2P];
    const float4* f4 = (const float4*)(features + (size_t)p * FF);
    float4* o4 = (float4*)(out_feats + (size_t)p * FF);
#pragma unroll
    for (int i = 0; i < FF / 4; i++) {
        float4 v = f4[i];
        o4[i] = v;
        x2[2 * i]     = __floats2half2_rn(v.x, v.y);
        x2[2 * i + 1] = __floats2half2_rn(v.z, v.w);
    }
    const float* pp = points + (size_t)p * 3;
    x2[32] = __floats2half2_rn(pp[0], pp[1]);
    x2[33] = __floats2half2_rn(pp[2], 0.f);
    x2[34] = __floats2half2_rn(1.f, 0.f);     // bias slot
    x2[35] = __floats2half2_rn(0.f, 0.f);

    // ---- layer-2 accumulators initialized with bias (in lane 0) ----
    __half2 h2acc[H2];
#pragma unroll
    for (int i = 0; i < H2; i++) h2acc[i] = __floats2half2_rn(sb2[i], 0.f);

    // ---- layer 1 in groups of 8 outputs, streamed into layer 2 ----
    for (int jg = 0; jg < H1 / 8; jg++) {   // NOT unrolled: bounds code size
        float h[8];
#pragma unroll
        for (int jj = 0; jj < 8; jj++) {
            const uint4* row = reinterpret_cast<const uint4*>(sW1h[jg * 8 + jj]);
            __half2 aa = __floats2half2_rn(0.f, 0.f);
            __half2 ab = __floats2half2_rn(0.f, 0.f);
#pragma unroll
            for (int q = 0; q < 9; q++) {
                uint4 w = row[q];
                aa = __hfma2(u2h2(w.x), x2[4 * q],     aa);
                ab = __hfma2(u2h2(w.y), x2[4 * q + 1], ab);
                aa = __hfma2(u2h2(w.z), x2[4 * q + 2], aa);
                ab = __hfma2(u2h2(w.w), x2[4 * q + 3], ab);
            }
            float2 f = __half22float2(__hadd2(aa, ab));
            h[jj] = fmaxf(f.x + f.y, 0.f);
        }
        __half2 hp[4];
#pragma unroll
        for (int t = 0; t < 4; t++) hp[t] = __floats2half2_rn(h[2 * t], h[2 * t + 1]);

        // fold 8 fresh h1 values into all 32 h2 accumulators (1 uint4 each)
#pragma unroll
        for (int i = 0; i < H2; i++) {
            uint4 w = reinterpret_cast<const uint4*>(sW2h[i])[jg];
            h2acc[i] = __hfma2(u2h2(w.x), hp[0], h2acc[i]);
            h2acc[i] = __hfma2(u2h2(w.y), hp[1], h2acc[i]);
            h2acc[i] = __hfma2(u2h2(w.z), hp[2], h2acc[i]);
            h2acc[i] = __hfma2(u2h2(w.w), hp[3], h2acc[i]);
        }
    }

    // ---- layer 3 (fp32): relu(h2) dot W3, 4 chains ----
    float z0 = 0.f, z1 = 0.f, z2 = 0.f, z3 = 0.f;
#pragma unroll
    for (int i = 0; i < H2; i += 4) {
        float2 f0 = __half22float2(h2acc[i]);
        float2 f1 = __half22float2(h2acc[i + 1]);
        float2 f2 = __half22float2(h2acc[i + 2]);
        float2 f3 = __half22float2(h2acc[i + 3]);
        z0 += sW3[i]     * fmaxf(f0.x + f0.y, 0.f);
        z1 += sW3[i + 1] * fmaxf(f1.x + f1.y, 0.f);
        z2 += sW3[i + 2] * fmaxf(f2.x + f2.y, 0.f);
        z3 += sW3[i + 3] * fmaxf(f3.x + f3.y, 0.f);
    }
    float z = sb3 + (z0 + z1) + (z2 + z3);
    float s = 1.0f / (1.0f + expf(-z));

    scores[p] = (mask[p] != 0) ? s : 0.0f;
}

// ============================================================
// Kernel 2: per-batch confidence + n_leaf gate. 1024 threads.
// Mask count merged with score loading (one memory phase).
// clarity = unbiased masked var (masked-out scores are exactly 0),
// sel compaction ascending == the reference argsort order,
// distances of consecutive selected points, unbiased var, conf.
// ============================================================
__global__ __launch_bounds__(1024) void conf_kernel(
    const float* __restrict__ scores_in, const int* __restrict__ mask,
    const float* __restrict__ points,
    float* __restrict__ scores_out, float* __restrict__ conf_out)
{
    __shared__ int sel[NN];           // 32 KB
    __shared__ int wtot[32], woff[32];
    __shared__ float wsum[32], wsq[32], wsd[32], wsd2[32];
    __shared__ int s_cnt, s_nleaf;

    int b = blockIdx.x;
    int tid = threadIdx.x;
    int lane = tid & 31, warp = tid >> 5;
    const float* s = scores_in + b * NN;
    float* so = scores_out + b * NN;
    const float* P = points + (size_t)b * NN * 3;

    // phase A: load mask (count) and scores together
    int base = tid * 8;
    float v8[8];
    {
        const float4* s4 = (const float4*)(s + base);
        float4 va = s4[0], vb = s4[1];
        v8[0] = va.x; v8[1] = va.y; v8[2] = va.z; v8[3] = va.w;
        v8[4] = vb.x; v8[5] = vb.y; v8[6] = vb.z; v8[7] = vb.w;
    }
    {
        const int4* m4 = (const int4*)(mask + b * NN);
        int4 ma = m4[tid * 2], mb = m4[tid * 2 + 1];
        int c = (ma.x != 0) + (ma.y != 0) + (ma.z != 0) + (ma.w != 0)
              + (mb.x != 0) + (mb.y != 0) + (mb.z != 0) + (mb.w != 0);
        for (int o = 16; o; o >>= 1) c += __shfl_down_sync(0xFFFFFFFFu, c, o);
        if (lane == 0) wtot[warp] = c;
    }
    __syncthreads();
    if (tid == 0) {
        int t = 0;
        for (int w = 0; w < 32; w++) t += wtot[w];
        s_nleaf = t;
    }
    __syncthreads();
    int nleaf = s_nleaf;
    if (nleaf < 10) {
        // reference zeroes all scores for this batch
        float4 zz = make_float4(0.f, 0.f, 0.f, 0.f);
        ((float4*)(so + base))[0] = zz;
        ((float4*)(so + base))[1] = zz;
#pragma unroll
        for (int i = 0; i < 8; i++) v8[i] = 0.0f;
    }

    // phase B: sums + per-thread selected count
    float sum = 0.0f, sumsq = 0.0f;
    int c = 0;
#pragma unroll
    for (int i = 0; i < 8; i++) {
        float v = v8[i];
        sum += v; sumsq += v * v;
        c += (v > 0.7f);
    }
    int incl = c;
    for (int o = 1; o < 32; o <<= 1) {
        int t = __shfl_up_sync(0xFFFFFFFFu, incl, o);
        if (lane >= o) incl += t;
    }
    if (lane == 31) wtot[warp] = incl;
    float rs = sum, rq = sumsq;
    for (int o = 16; o; o >>= 1) {
        rs += __shfl_down_sync(0xFFFFFFFFu, rs, o);
        rq += __shfl_down_sync(0xFFFFFFFFu, rq, o);
    }
    if (lane == 0) { wsum[warp] = rs; wsq[warp] = rq; }
    __syncthreads();
    if (warp == 0) {
        int t = wtot[lane];
        int sc = t;
        for (int o = 1; o < 32; o <<= 1) {
            int u = __shfl_up_sync(0xFFFFFFFFu, sc, o);
            if (lane >= o) sc += u;
        }
        woff[lane] = sc - t;
        if (lane == 31) s_cnt = sc;
    }
    __syncthreads();

    // phase C: write selected indices in ascending order
    int off = woff[warp] + incl - c;
#pragma unroll
    for (int i = 0; i < 8; i++) {
        if (v8[i] > 0.7f) sel[off++] = base + i;
    }
    __syncthreads();

    int cnt = s_cnt;
    int pc = cnt - 1;
    float sd = 0.0f, sd2 = 0.0f;
    for (int q = tid; q < pc; q += 1024) {
        int i1 = sel[q], i2 = sel[q + 1];
        float dx = P[i2 * 3 + 0] - P[i1 * 3 + 0];
        float dy = P[i2 * 3 + 1] - P[i1 * 3 + 1];
        float dz = P[i2 * 3 + 2] - P[i1 * 3 + 2];
        float d = sqrtf(dx * dx + dy * dy + dz * dz);
        sd += d; sd2 += d * d;
    }
    for (int o = 16; o; o >>= 1) {
        sd  += __shfl_down_sync(0xFFFFFFFFu, sd, o);
        sd2 += __shfl_down_sync(0xFFFFFFFFu, sd2, o);
    }
    if (lane == 0) { wsd[warp] = sd; wsd2[warp] = sd2; }
    __syncthreads();

    if (tid == 0) {
        float tsum = 0.f, tsq = 0.f, tsd = 0.f, tsd2 = 0.f;
        for (int w = 0; w < 32; w++) {
            tsum += wsum[w]; tsq += wsq[w]; tsd += wsd[w]; tsd2 += wsd2[w];
        }
        float nl = (float)nleaf;
        float mean = tsum / fmaxf(nl, 1.0f);
        float clarity = (tsq - 2.0f * mean * tsum + mean * mean * nl)
                        / fmaxf(nl - 1.0f, 1.0f);
        float pcf = (float)(pc > 0 ? pc : 0);
        float meand = tsd / fmaxf(pcf, 1.0f);
        float dvar = (tsd2 - 2.0f * meand * tsd + meand * meand * pcf)
                     / fmaxf(pcf - 1.0f, 1.0f);
        float cont = fminf(fmaxf(1.0f / (dvar + 1e-8f), 0.0f), 1.0f);
        cont = (cnt > 5) ? cont : 0.0f;
        float conf = fminf(fmaxf(clarity * cont, 0.0f), 1.0f);
        conf = (nleaf == 0) ? 0.0f : conf;
        conf_out[b] = conf;
    }
}

// ============================================================
// launch
// ============================================================
extern "C" void kernel_launch(void* const* d_in, const int* in_sizes, int n_in,
                              void* d_out, int out_size) {
    const float* points   = (const float*)d_in[0];
    const float* features = (const float*)d_in[1];
    const int*   mask     = (const int*)d_in[2];
    const float* W1 = (const float*)d_in[3];
    const float* b1 = (const float*)d_in[4];
    const float* W2 = (const float*)d_in[5];
    const float* b2 = (const float*)d_in[6];
    const float* W3 = (const float*)d_in[7];
    const float* b3 = (const float*)d_in[8];

    float* out_scores = (float*)d_out;                       // [B*N]
    float* out_feats  = out_scores + BB * NN;                // [B*N*F]
    float* out_conf   = out_feats + (size_t)BB * NN * FF;    // [B]

    mlp_kernel<<<(BB * NN) / 256, 256>>>(points, features, mask,
                                         W1, b1, W2, b2, W3, b3,
                                         out_scores, out_feats);

    conf_kernel<<<BB, 1024>>>(out_scores, mask, points, out_scores, out_conf);
}